// round 7
// baseline (speedup 1.0000x reference)
#include <cuda_runtime.h>
#include <cuda_bf16.h>

#define B_ 2048
#define S_ 277
#define R_ 80
#define L_ 12
#define Z_ 56
#define NROWS (B_ * S_)          // 567296, divisible by 8
#define NBATCH (NROWS / 8)       // 70912 warp-batches
#define VBLOCKS 64
#define VCHUNK (B_ / VBLOCKS)    // 32
#define TPB 256
#define WPB (TPB / 32)
#define FULL 0xffffffffu
#define R4 (R_ / 4)              // 20 float4 per row

__device__ double g_bce;
__device__ float  g_var[Z_ * Z_];
__device__ float  g_avg[Z_];
__device__ unsigned g_ticket;

__global__ void __launch_bounds__(TPB, 4) mega_kernel(
    const float* __restrict__ x,
    const float* __restrict__ rx,
    const float* __restrict__ mu,
    const float* __restrict__ masks,
    const int*   __restrict__ lhs,
    float* __restrict__ out)
{
    __shared__ float  smem_buf[VCHUNK * Z_];      // var tile / final reduce
    __shared__ float4 smask4[L_ * R4];
    __shared__ int    slhs[R_];
    __shared__ float  swacc[WPB];
    __shared__ bool   s_last;

    const int tid = threadIdx.x;
    const int bid = blockIdx.x;

    {
        const float4* m4 = (const float4*)masks;
        for (int i = tid; i < L_ * R4; i += TPB) smask4[i] = m4[i];
        if (tid < R_) slhs[tid] = lhs[tid];
    }
    __syncthreads();

    // ---------------- var path: first VBLOCKS blocks do mu^T mu tile ------
    if (bid < VBLOCKS) {
        const int b0 = bid * VCHUNK;
        for (int i = tid; i < VCHUNK * Z_; i += TPB)
            smem_buf[i] = mu[(size_t)b0 * Z_ + i];
        __syncthreads();
        if (tid < Z_) {
            float s = 0.f;
            #pragma unroll
            for (int b = 0; b < VCHUNK; b++) s += smem_buf[b * Z_ + tid];
            atomicAdd(&g_avg[tid], s);
        }
        for (int p = tid; p < Z_ * Z_; p += TPB) {
            const int i = p / Z_, j = p % Z_;
            float s = 0.f;
            #pragma unroll
            for (int b = 0; b < VCHUNK; b++)
                s += smem_buf[b * Z_ + i] * smem_buf[b * Z_ + j];
            atomicAdd(&g_var[p], s);
        }
    }

    // ---------------- bce: 8 rows per warp, 4 lanes per row ----------------
    const int lane = tid & 31;
    const int warp = tid >> 5;
    const int sr   = lane >> 2;          // sub-row 0..7
    const int g    = lane & 3;           // chunk  0..3
    const int gw   = bid * WPB + warp;
    const int nw   = gridDim.x * WPB;
    const int cbase = sr * R4 + g;       // float4 index within 8-row batch

    float acc = 0.f;

    float4 xv[5], rv[5];
    if (gw < NBATCH) {                   // prologue loads for first batch
        const float4* xb = (const float4*)(x  + (size_t)gw * 8 * R_);
        const float4* rb = (const float4*)(rx + (size_t)gw * 8 * R_);
        #pragma unroll
        for (int k = 0; k < 5; k++) xv[k] = __ldcs(xb + cbase + 4 * k);
        #pragma unroll
        for (int k = 0; k < 5; k++) rv[k] = __ldcs(rb + cbase + 4 * k);
    }

    #pragma unroll 2
    for (int bat = gw; bat < NBATCH; bat += nw) {
        // next-batch pointers (clamped to current batch on last iteration;
        // the extra loads are discarded -> branchless pipeline)
        const int nxt = (bat + nw < NBATCH) ? (bat + nw) : bat;
        const float4* xbn = (const float4*)(x  + (size_t)nxt * 8 * R_);
        const float4* rbn = (const float4*)(rx + (size_t)nxt * 8 * R_);

        // pass 1a: true index from x only (2 accumulators)
        float tr0 = 0.f, tr1 = 0.f;
        #pragma unroll
        for (int k = 0; k < 5; k++) {
            const float i0 = (float)(4 * g + 16 * k);
            tr0 = fmaf(xv[k].x, i0,       tr0);
            tr1 = fmaf(xv[k].y, i0 + 1.f, tr1);
            tr0 = fmaf(xv[k].z, i0 + 2.f, tr0);
            tr1 = fmaf(xv[k].w, i0 + 3.f, tr1);
        }
        // pass 1b: p_true = sum(x * r) (2 accumulators)
        float rt0 = 0.f, rt1 = 0.f;
        #pragma unroll
        for (int k = 0; k < 5; k++) {
            rt0 = fmaf(xv[k].x, rv[k].x, rt0);
            rt1 = fmaf(xv[k].y, rv[k].y, rt1);
            rt0 = fmaf(xv[k].z, rv[k].z, rt0);
            rt1 = fmaf(xv[k].w, rv[k].w, rt1);
        }

        // xv is dead: prefetch next batch's x now (overlaps rest of compute)
        float4 xq[5];
        #pragma unroll
        for (int k = 0; k < 5; k++) xq[k] = __ldcs(xbn + cbase + 4 * k);

        float trp = tr0 + tr1, rtp = rt0 + rt1;
        trp += __shfl_xor_sync(FULL, trp, 1);
        rtp += __shfl_xor_sync(FULL, rtp, 1);
        trp += __shfl_xor_sync(FULL, trp, 2);
        rtp += __shfl_xor_sync(FULL, rtp, 2);

        const int lrow = slhs[__float2int_rn(trp)];

        // pass 2: p = r*mask in place; row sum (2 accumulators)
        float s0 = 0.f, s1 = 0.f;
        #pragma unroll
        for (int k = 0; k < 5; k++) {
            const float4 m = smask4[lrow * R4 + g + 4 * k];
            rv[k].x *= m.x;  rv[k].y *= m.y;
            rv[k].z *= m.z;  rv[k].w *= m.w;
            s0 += rv[k].x + rv[k].y;
            s1 += rv[k].z + rv[k].w;
        }
        float s = s0 + s1;
        s += __shfl_xor_sync(FULL, s, 1);
        s += __shfl_xor_sync(FULL, s, 2);
        const float inv = __fdividef(1.0f, s);

        // pass 3: product of (1 - o_r) over ALL r (2 accumulators)
        float pa = 1.f, pb = 1.f;
        #pragma unroll
        for (int k = 0; k < 5; k++) {
            pa *= fmaf(-rv[k].x, inv, 1.f) * fmaf(-rv[k].y, inv, 1.f);
            pb *= fmaf(-rv[k].z, inv, 1.f) * fmaf(-rv[k].w, inv, 1.f);
        }
        float pr = pa * pb;
        pr *= __shfl_xor_sync(FULL, pr, 1);
        pr *= __shfl_xor_sync(FULL, pr, 2);

        // rv is dead: prefetch next batch's rx now
        #pragma unroll
        for (int k = 0; k < 5; k++) rv[k] = __ldcs(rbn + cbase + 4 * k);

        // log(o_true) + sum_{r != true} log(1-o_r)
        const float ot  = rtp * inv;
        const float omt = fmaf(-rtp, inv, 1.f);
        acc += __logf(__fdividef(ot * pr, omt));

        #pragma unroll
        for (int k = 0; k < 5; k++) xv[k] = xq[k];
    }

    acc *= 0.25f;                          // each row counted by 4 lanes
    #pragma unroll
    for (int o = 16; o; o >>= 1) acc += __shfl_xor_sync(FULL, acc, o);
    if (lane == 0) swacc[warp] = acc;
    __syncthreads();
    if (tid == 0) {
        float t = 0.f;
        #pragma unroll
        for (int w2 = 0; w2 < WPB; w2++) t += swacc[w2];
        atomicAdd(&g_bce, (double)t);
    }

    // ---------------- ticket + last-block finalize -------------------------
    __threadfence();
    __syncthreads();
    if (tid == 0) {
        const unsigned t = atomicAdd(&g_ticket, 1u);
        s_last = (t == gridDim.x - 1);
    }
    __syncthreads();
    if (!s_last) return;
    __threadfence();

    float contrib = 0.f;
    for (int p = tid; p < Z_ * Z_; p += TPB) {
        const float v = fmaf(g_var[p], 1.0f / B_,
                             ((p / Z_) == (p % Z_)) ? -1.0f : 0.0f);
        contrib += fabsf(v);
        g_var[p] = 0.f;                          // reset for graph replay
    }
    contrib *= 1.0f / ((float)Z_ * (float)Z_);
    if (tid < Z_) {
        const float m = g_avg[tid] * (1.0f / B_);
        contrib += m * m * (1.0f / Z_);
        g_avg[tid] = 0.f;
    }
    smem_buf[tid] = contrib;
    __syncthreads();
    for (int o = TPB / 2; o; o >>= 1) {
        if (tid < o) smem_buf[tid] += smem_buf[tid + o];
        __syncthreads();
    }
    if (tid == 0) {
        const double bce = -g_bce / ((double)S_ * (double)B_);
        out[0] = (float)(bce + (double)smem_buf[0]);
        g_bce = 0.0;
        g_ticket = 0u;
    }
}

extern "C" void kernel_launch(void* const* d_in, const int* in_sizes, int n_in,
                              void* d_out, int out_size) {
    const float* x     = (const float*)d_in[0];
    const float* rx    = (const float*)d_in[1];
    const float* mu    = (const float*)d_in[2];
    // d_in[3] = log_var (unused by the reference)
    const float* masks = (const float*)d_in[4];
    const int*   lhs   = (const int*)d_in[5];
    float* out = (float*)d_out;

    int dev = 0;
    cudaGetDevice(&dev);
    int sms = 148;
    cudaDeviceGetAttribute(&sms, cudaDevAttrMultiProcessorCount, dev);
    int nb = 0;
    cudaOccupancyMaxActiveBlocksPerMultiprocessor(&nb, mega_kernel, TPB, 0);
    if (nb < 1) nb = 1;
    int grid = sms * nb;                 // one resident wave
    if (grid < VBLOCKS + 1) grid = VBLOCKS + 1;

    mega_kernel<<<grid, TPB>>>(x, rx, mu, masks, lhs, out);
}

// round 8
// speedup vs baseline: 1.2088x; 1.2088x over previous
#include <cuda_runtime.h>
#include <cuda_bf16.h>
#include <cstdint>

#define B_ 2048
#define S_ 277
#define R_ 80
#define L_ 12
#define Z_ 56
#define NROWS (B_ * S_)          // 567296
#define TROWS 64                 // rows per tile
#define NTILES (NROWS / TROWS)   // 8864 exactly
#define VBLOCKS 64
#define VCHUNK (B_ / VBLOCKS)    // 32
#define TPB 256
#define WPB (TPB / 32)
#define FULL 0xffffffffu
#define R4 (R_ / 4)              // 20 float4 per row
#define PADF 84                  // padded floats per row in smem (336B, 16B-aligned)

// dynamic smem layout (bytes)
#define OFF_SRX   0                                   // 2 stages * 64 * 84 floats
#define SRX_STAGE (TROWS * PADF)                      // floats per stage
#define OFF_SIDX  (2 * SRX_STAGE * 4)                 // 43008: 2 * 64 ints
#define OFF_MASK  (OFF_SIDX + 2 * TROWS * 4)          // 43520: 240 float4
#define OFF_LHS   (OFF_MASK + L_ * R4 * 16)           // 47360: 80 ints
#define OFF_WACC  (OFF_LHS + 320)                     // 47680: 8 floats
#define OFF_LAST  (OFF_WACC + 32)                     // 47712: 1 int
#define SMEM_TOTAL 47744

__device__ double g_bce;
__device__ float  g_var[Z_ * Z_];
__device__ float  g_avg[Z_];
__device__ unsigned g_ticket;

__device__ __forceinline__ void cp_async16(uint32_t saddr, const void* gptr) {
    asm volatile("cp.async.cg.shared.global [%0], [%1], 16;"
                 :: "r"(saddr), "l"(gptr));
}
#define CP_COMMIT() asm volatile("cp.async.commit_group;" ::: "memory")
#define CP_WAIT1()  asm volatile("cp.async.wait_group 1;" ::: "memory")

__global__ void __launch_bounds__(TPB, 4) mega_kernel(
    const float* __restrict__ x,
    const float* __restrict__ rx,
    const float* __restrict__ mu,
    const float* __restrict__ masks,
    const int*   __restrict__ lhs,
    float* __restrict__ out)
{
    extern __shared__ char dsm[];
    float*  srx    = (float*)(dsm + OFF_SRX);
    int*    sidx   = (int*)(dsm + OFF_SIDX);
    float4* smask4 = (float4*)(dsm + OFF_MASK);
    int*    slhs   = (int*)(dsm + OFF_LHS);
    float*  swacc  = (float*)(dsm + OFF_WACC);
    int*    s_last = (int*)(dsm + OFF_LAST);
    const uint32_t srx_s = (uint32_t)__cvta_generic_to_shared(srx);

    const int tid = threadIdx.x;
    const int bid = blockIdx.x;
    const int G   = gridDim.x;

    {
        const float4* m4 = (const float4*)masks;
        for (int i = tid; i < L_ * R4; i += TPB) smask4[i] = m4[i];
        if (tid < R_) slhs[tid] = lhs[tid];
    }

    // ---------------- var path: first VBLOCKS blocks do mu^T mu tile ------
    if (bid < VBLOCKS) {
        __syncthreads();                       // masks done before reuse check
        float* vbuf = srx;                     // reuse stage buffer
        const int b0 = bid * VCHUNK;
        for (int i = tid; i < VCHUNK * Z_; i += TPB)
            vbuf[i] = mu[(size_t)b0 * Z_ + i];
        __syncthreads();
        if (tid < Z_) {
            float s = 0.f;
            #pragma unroll
            for (int b = 0; b < VCHUNK; b++) s += vbuf[b * Z_ + tid];
            atomicAdd(&g_avg[tid], s);
        }
        for (int p = tid; p < Z_ * Z_; p += TPB) {
            const int i = p / Z_, j = p % Z_;
            float s = 0.f;
            #pragma unroll
            for (int b = 0; b < VCHUNK; b++)
                s += vbuf[b * Z_ + i] * vbuf[b * Z_ + j];
            atomicAdd(&g_var[p], s);
        }
    }
    __syncthreads();

    // ---------------- bce pipeline ------------------------------------------
    const int lane = tid & 31;
    const int warp = tid >> 5;

    // loader lambda-ish: tile -> stage st
    const float4* xb4 = (const float4*)x;
    const float4* rb4 = (const float4*)rx;

    #define LOAD_TILE(TILE, ST) do {                                          \
        const size_t fb = (size_t)(TILE) * (TROWS * R4);                      \
        _Pragma("unroll")                                                     \
        for (int u = 0; u < 5; u++) {                                         \
            const int i = tid + u * TPB;                                      \
            const int row_ = i / R4, col_ = i - row_ * R4;                    \
            cp_async16(srx_s + ((ST) * SRX_STAGE + row_ * PADF + col_ * 4) * 4,\
                       rb4 + fb + i);                                         \
        }                                                                     \
        float4 xs[5];                                                         \
        _Pragma("unroll")                                                     \
        for (int u = 0; u < 5; u++) xs[u] = __ldcs(xb4 + fb + tid + u * TPB); \
        _Pragma("unroll")                                                     \
        for (int u = 0; u < 5; u++) {                                         \
            const int i = tid + u * TPB;                                      \
            const int row_ = i / R4, col_ = i - row_ * R4;                    \
            const float4 v = xs[u];                                           \
            if (v.x > 0.5f || v.y > 0.5f || v.z > 0.5f || v.w > 0.5f) {       \
                const int j = v.y > 0.5f ? 1 : (v.z > 0.5f ? 2 :              \
                              (v.w > 0.5f ? 3 : 0));                          \
                sidx[(ST) * TROWS + row_] = col_ * 4 + j;                     \
            }                                                                 \
        }                                                                     \
    } while (0)

    // prologue: two tiles in flight
    LOAD_TILE(bid, 0);
    CP_COMMIT();
    if (bid + G < NTILES) LOAD_TILE(bid + G, 1);
    CP_COMMIT();

    const int sr = lane >> 2;        // sub-row 0..7 within warp's 8 rows
    const int g  = lane & 3;         // float4 group 0..3
    float acc = 0.f;
    int stage = 0;

    for (int t = bid; t < NTILES; t += G) {
        CP_WAIT1();                   // this stage's rx resident
        __syncthreads();              // block-wide visibility (cp.async + sidx)

        {
            const int row   = warp * 8 + sr;
            const float* rp = srx + stage * SRX_STAGE + row * PADF;
            const int  tix  = sidx[stage * TROWS + row];
            const int  lrow = slhs[tix];
            const float pt  = rp[tix];          // p_true (mask==1 at true rule)

            const float4* rp4 = (const float4*)rp;
            float4 rv[5];
            #pragma unroll
            for (int k = 0; k < 5; k++) rv[k] = rp4[g + 4 * k];

            float s0 = 0.f, s1 = 0.f;
            #pragma unroll
            for (int k = 0; k < 5; k++) {
                const float4 m = smask4[lrow * R4 + g + 4 * k];
                rv[k].x *= m.x;  rv[k].y *= m.y;
                rv[k].z *= m.z;  rv[k].w *= m.w;
                s0 += rv[k].x + rv[k].y;
                s1 += rv[k].z + rv[k].w;
            }
            float s = s0 + s1;
            s += __shfl_xor_sync(FULL, s, 1);
            s += __shfl_xor_sync(FULL, s, 2);
            const float inv = __fdividef(1.0f, s);

            float pa = 1.f, pb = 1.f;
            #pragma unroll
            for (int k = 0; k < 5; k++) {
                pa *= fmaf(-rv[k].x, inv, 1.f) * fmaf(-rv[k].y, inv, 1.f);
                pb *= fmaf(-rv[k].z, inv, 1.f) * fmaf(-rv[k].w, inv, 1.f);
            }
            float pr = pa * pb;
            pr *= __shfl_xor_sync(FULL, pr, 1);
            pr *= __shfl_xor_sync(FULL, pr, 2);

            const float ot  = pt * inv;
            const float omt = fmaf(-pt, inv, 1.f);
            acc += __logf(__fdividef(ot * pr, omt));   // true factor divided out
        }

        __syncthreads();              // all done reading this stage
        if (t + 2 * G < NTILES) LOAD_TILE(t + 2 * G, stage);
        CP_COMMIT();                  // keep group accounting uniform
        stage ^= 1;
    }

    acc *= 0.25f;                     // each row counted by 4 lanes
    #pragma unroll
    for (int o = 16; o; o >>= 1) acc += __shfl_xor_sync(FULL, acc, o);
    if (lane == 0) swacc[warp] = acc;
    __syncthreads();
    if (tid == 0) {
        float tsum = 0.f;
        #pragma unroll
        for (int w2 = 0; w2 < WPB; w2++) tsum += swacc[w2];
        atomicAdd(&g_bce, (double)tsum);
    }

    // ---------------- ticket + last-block finalize -------------------------
    __threadfence();
    __syncthreads();
    if (tid == 0) {
        const unsigned tk = atomicAdd(&g_ticket, 1u);
        *s_last = (tk == (unsigned)(G - 1)) ? 1 : 0;
    }
    __syncthreads();
    if (!*s_last) return;
    __threadfence();

    float* red = srx;                 // reuse stage buffer for final reduce
    float contrib = 0.f;
    for (int p = tid; p < Z_ * Z_; p += TPB) {
        const float v = fmaf(g_var[p], 1.0f / B_,
                             ((p / Z_) == (p % Z_)) ? -1.0f : 0.0f);
        contrib += fabsf(v);
        g_var[p] = 0.f;               // reset for graph replay
    }
    contrib *= 1.0f / ((float)Z_ * (float)Z_);
    if (tid < Z_) {
        const float m = g_avg[tid] * (1.0f / B_);
        contrib += m * m * (1.0f / Z_);
        g_avg[tid] = 0.f;
    }
    red[tid] = contrib;
    __syncthreads();
    for (int o = TPB / 2; o; o >>= 1) {
        if (tid < o) red[tid] += red[tid + o];
        __syncthreads();
    }
    if (tid == 0) {
        const double bce = -g_bce / ((double)S_ * (double)B_);
        out[0] = (float)(bce + (double)red[0]);
        g_bce = 0.0;
        g_ticket = 0u;
    }
}

extern "C" void kernel_launch(void* const* d_in, const int* in_sizes, int n_in,
                              void* d_out, int out_size) {
    const float* x     = (const float*)d_in[0];
    const float* rx    = (const float*)d_in[1];
    const float* mu    = (const float*)d_in[2];
    // d_in[3] = log_var (unused by the reference)
    const float* masks = (const float*)d_in[4];
    const int*   lhs   = (const int*)d_in[5];
    float* out = (float*)d_out;

    cudaFuncSetAttribute(mega_kernel,
                         cudaFuncAttributeMaxDynamicSharedMemorySize, SMEM_TOTAL);

    int dev = 0;
    cudaGetDevice(&dev);
    int sms = 148;
    cudaDeviceGetAttribute(&sms, cudaDevAttrMultiProcessorCount, dev);
    int nb = 0;
    cudaOccupancyMaxActiveBlocksPerMultiprocessor(&nb, mega_kernel, TPB, SMEM_TOTAL);
    if (nb < 1) nb = 1;
    int grid = sms * nb;                 // one resident wave
    if (grid < VBLOCKS + 1) grid = VBLOCKS + 1;
    if (grid > NTILES) grid = NTILES;

    mega_kernel<<<grid, TPB, SMEM_TOTAL>>>(x, rx, mu, masks, lhs, out);
}